// round 3
// baseline (speedup 1.0000x reference)
#include <cuda_runtime.h>

#define N_NODES 100000
#define N_EDGES 3200000
#define G_GROUPS 128
#define F_IN 9
#define H_DIM 64

// Scratch (no allocation allowed -> __device__ globals). 16B-aligned: accessed
// with 128-bit loads/stores and red.global.add.v4.f32.
__device__ __align__(16) float g_h1[N_NODES * H_DIM];   // hidden after conv1
__device__ __align__(16) float g_agg[N_NODES * H_DIM];  // aggregation buffer
__device__ __align__(16) float g_pi[N_NODES];           // masked sigmoid output
__device__ __align__(16) float g_texp[G_GROUPS];        // per-group expenses

__device__ __forceinline__ void red_add_v4(float* addr, float a, float b, float c, float d) {
    asm volatile("red.global.add.v4.f32 [%0], {%1,%2,%3,%4};"
                 :: "l"(addr), "f"(a), "f"(b), "f"(c), "f"(d) : "memory");
}

// ---------------------------------------------------------------------------
__global__ void zero_agg_kernel() {
    int idx = blockIdx.x * blockDim.x + threadIdx.x;
    const int total4 = N_NODES * H_DIM / 4;
    float4* p = reinterpret_cast<float4*>(g_agg);
    float4 z = make_float4(0.f, 0.f, 0.f, 0.f);
    for (int i = idx; i < total4; i += gridDim.x * blockDim.x) p[i] = z;
}

// ---------------------------------------------------------------------------
// Edge pass 1: msg = relu(x[src] + edge_attr*We1 + be1), scatter-add at dst.
// agg stored with row stride 12 so v4 reds stay 16B-aligned (48B rows).
__global__ void edge1_kernel(const float* __restrict__ x,
                             const int* __restrict__ ei,
                             const float* __restrict__ eattr,
                             const float* __restrict__ We1,
                             const float* __restrict__ be1) {
    int e = blockIdx.x * blockDim.x + threadIdx.x;
    if (e >= N_EDGES) return;
    int s = __ldg(&ei[e]);
    int d = __ldg(&ei[N_EDGES + e]);
    float a = __ldg(&eattr[e]);
    float m[9];
#pragma unroll
    for (int f = 0; f < 9; f++) {
        float v = __ldg(&x[s * 9 + f]) + fmaf(a, __ldg(&We1[f]), __ldg(&be1[f]));
        m[f] = fmaxf(v, 0.f);
    }
    float* base = &g_agg[d * 12];
    red_add_v4(base + 0, m[0], m[1], m[2], m[3]);
    red_add_v4(base + 4, m[4], m[5], m[6], m[7]);
    red_add_v4(base + 8, m[8], 0.f, 0.f, 0.f);
}

// ---------------------------------------------------------------------------
// Node MLP 1: z = x + agg; h1 = relu(relu(z@W1a+b1a)@W1b+b1b)
__global__ void mlp1_kernel(const float* __restrict__ x,
                            const float* __restrict__ W1a, const float* __restrict__ b1a,
                            const float* __restrict__ W1b, const float* __restrict__ b1b) {
    __shared__ __align__(16) float sWa[F_IN * H_DIM];
    __shared__ __align__(16) float sWb[H_DIM * H_DIM];
    __shared__ __align__(16) float sba[H_DIM];
    __shared__ __align__(16) float sbb[H_DIM];
    int tid = threadIdx.x;
    for (int i = tid; i < F_IN * H_DIM; i += blockDim.x) sWa[i] = W1a[i];
    for (int i = tid; i < H_DIM * H_DIM; i += blockDim.x) sWb[i] = W1b[i];
    if (tid < H_DIM) { sba[tid] = b1a[tid]; sbb[tid] = b1b[tid]; }
    if (blockIdx.x == 0 && tid < G_GROUPS) g_texp[tid] = 0.f;  // runs before mlp2
    __syncthreads();

    int n = blockIdx.x * blockDim.x + tid;
    if (n >= N_NODES) return;

    float z[F_IN];
#pragma unroll
    for (int f = 0; f < F_IN; f++) z[f] = x[n * 9 + f] + g_agg[n * 12 + f];

    float t[H_DIM];
#pragma unroll
    for (int j = 0; j < H_DIM; j += 4) {
        float4 acc = *reinterpret_cast<float4*>(&sba[j]);
#pragma unroll
        for (int f = 0; f < F_IN; f++) {
            float4 w = *reinterpret_cast<float4*>(&sWa[f * H_DIM + j]);
            acc.x = fmaf(z[f], w.x, acc.x);
            acc.y = fmaf(z[f], w.y, acc.y);
            acc.z = fmaf(z[f], w.z, acc.z);
            acc.w = fmaf(z[f], w.w, acc.w);
        }
        t[j + 0] = fmaxf(acc.x, 0.f);
        t[j + 1] = fmaxf(acc.y, 0.f);
        t[j + 2] = fmaxf(acc.z, 0.f);
        t[j + 3] = fmaxf(acc.w, 0.f);
    }

    for (int j = 0; j < H_DIM; j += 4) {
        float4 acc = *reinterpret_cast<float4*>(&sbb[j]);
#pragma unroll
        for (int k = 0; k < H_DIM; k++) {
            float4 w = *reinterpret_cast<float4*>(&sWb[k * H_DIM + j]);
            acc.x = fmaf(t[k], w.x, acc.x);
            acc.y = fmaf(t[k], w.y, acc.y);
            acc.z = fmaf(t[k], w.z, acc.z);
            acc.w = fmaf(t[k], w.w, acc.w);
        }
        float4 o;
        o.x = fmaxf(acc.x, 0.f);
        o.y = fmaxf(acc.y, 0.f);
        o.z = fmaxf(acc.z, 0.f);
        o.w = fmaxf(acc.w, 0.f);
        *reinterpret_cast<float4*>(&g_h1[n * H_DIM + j]) = o;
    }
}

// ---------------------------------------------------------------------------
// Edge pass 2: 16 threads per edge, 4 features each.
__global__ void edge2_kernel(const int* __restrict__ ei,
                             const float* __restrict__ eattr,
                             const float* __restrict__ We2,
                             const float* __restrict__ be2) {
    int t = blockIdx.x * blockDim.x + threadIdx.x;
    int e = t >> 4;
    int lane = (t & 15) << 2;  // feature base: 0,4,...,60
    if (e >= N_EDGES) return;
    int s = __ldg(&ei[e]);
    int d = __ldg(&ei[N_EDGES + e]);
    float a = __ldg(&eattr[e]);
    float4 w = __ldg(reinterpret_cast<const float4*>(&We2[lane]));
    float4 b = __ldg(reinterpret_cast<const float4*>(&be2[lane]));
    float4 h = *reinterpret_cast<const float4*>(&g_h1[s * H_DIM + lane]);
    float m0 = fmaxf(h.x + fmaf(a, w.x, b.x), 0.f);
    float m1 = fmaxf(h.y + fmaf(a, w.y, b.y), 0.f);
    float m2 = fmaxf(h.z + fmaf(a, w.z, b.z), 0.f);
    float m3 = fmaxf(h.w + fmaf(a, w.w, b.w), 0.f);
    red_add_v4(&g_agg[d * H_DIM + lane], m0, m1, m2, m3);
}

// ---------------------------------------------------------------------------
// Node MLP 2 + readout head + group segment-sum of expenses.
__global__ void mlp2_kernel(const float* __restrict__ W2a, const float* __restrict__ b2a,
                            const float* __restrict__ W2b, const float* __restrict__ b2b,
                            const float* __restrict__ Wr1, const float* __restrict__ br1,
                            const float* __restrict__ Wr2, const float* __restrict__ br2,
                            const int* __restrict__ batch,
                            const int* __restrict__ term,
                            const float* __restrict__ c_cost) {
    __shared__ __align__(16) float sWa[H_DIM * H_DIM];
    __shared__ __align__(16) float sWb[H_DIM * H_DIM];
    __shared__ __align__(16) float sWr1[H_DIM * 32];
    __shared__ __align__(16) float sba[H_DIM];
    __shared__ __align__(16) float sbb[H_DIM];
    __shared__ __align__(16) float sbr1[32];
    __shared__ __align__(16) float sWr2[32];
    __shared__ float sbr2;
    int tid = threadIdx.x;
    for (int i = tid; i < H_DIM * H_DIM; i += blockDim.x) { sWa[i] = W2a[i]; sWb[i] = W2b[i]; }
    for (int i = tid; i < H_DIM * 32; i += blockDim.x) sWr1[i] = Wr1[i];
    if (tid < H_DIM) { sba[tid] = b2a[tid]; sbb[tid] = b2b[tid]; }
    if (tid < 32) { sbr1[tid] = br1[tid]; sWr2[tid] = Wr2[tid]; }
    if (tid == 0) sbr2 = br2[0];
    __syncthreads();

    int n = blockIdx.x * blockDim.x + tid;
    if (n >= N_NODES) return;

    float z[H_DIM];
#pragma unroll
    for (int k = 0; k < H_DIM; k += 4) {
        float4 hv = *reinterpret_cast<const float4*>(&g_h1[n * H_DIM + k]);
        float4 av = *reinterpret_cast<const float4*>(&g_agg[n * H_DIM + k]);
        z[k + 0] = hv.x + av.x;
        z[k + 1] = hv.y + av.y;
        z[k + 2] = hv.z + av.z;
        z[k + 3] = hv.w + av.w;
    }

    float t[H_DIM];
    for (int j = 0; j < H_DIM; j += 4) {
        float4 acc = *reinterpret_cast<float4*>(&sba[j]);
#pragma unroll
        for (int k = 0; k < H_DIM; k++) {
            float4 w = *reinterpret_cast<float4*>(&sWa[k * H_DIM + j]);
            acc.x = fmaf(z[k], w.x, acc.x);
            acc.y = fmaf(z[k], w.y, acc.y);
            acc.z = fmaf(z[k], w.z, acc.z);
            acc.w = fmaf(z[k], w.w, acc.w);
        }
        t[j + 0] = fmaxf(acc.x, 0.f);
        t[j + 1] = fmaxf(acc.y, 0.f);
        t[j + 2] = fmaxf(acc.z, 0.f);
        t[j + 3] = fmaxf(acc.w, 0.f);
    }

    // reuse z[] as h2
    for (int j = 0; j < H_DIM; j += 4) {
        float4 acc = *reinterpret_cast<float4*>(&sbb[j]);
#pragma unroll
        for (int k = 0; k < H_DIM; k++) {
            float4 w = *reinterpret_cast<float4*>(&sWb[k * H_DIM + j]);
            acc.x = fmaf(t[k], w.x, acc.x);
            acc.y = fmaf(t[k], w.y, acc.y);
            acc.z = fmaf(t[k], w.z, acc.z);
            acc.w = fmaf(t[k], w.w, acc.w);
        }
        z[j + 0] = fmaxf(acc.x, 0.f);
        z[j + 1] = fmaxf(acc.y, 0.f);
        z[j + 2] = fmaxf(acc.z, 0.f);
        z[j + 3] = fmaxf(acc.w, 0.f);
    }

    // readout: r = relu(h2 @ Wr1 + br1) [32]; p = r @ Wr2 + br2
    float r[32];
    for (int j = 0; j < 32; j += 4) {
        float4 acc = *reinterpret_cast<float4*>(&sbr1[j]);
#pragma unroll
        for (int k = 0; k < H_DIM; k++) {
            float4 w = *reinterpret_cast<float4*>(&sWr1[k * 32 + j]);
            acc.x = fmaf(z[k], w.x, acc.x);
            acc.y = fmaf(z[k], w.y, acc.y);
            acc.z = fmaf(z[k], w.z, acc.z);
            acc.w = fmaf(z[k], w.w, acc.w);
        }
        r[j + 0] = fmaxf(acc.x, 0.f);
        r[j + 1] = fmaxf(acc.y, 0.f);
        r[j + 2] = fmaxf(acc.z, 0.f);
        r[j + 3] = fmaxf(acc.w, 0.f);
    }
    float p = sbr2;
#pragma unroll
    for (int k = 0; k < 32; k++) p = fmaf(r[k], sWr2[k], p);

    float pi = 1.f / (1.f + expf(-p));
    if (term[n] != 0) pi = 0.f;
    g_pi[n] = pi;
    atomicAdd(&g_texp[batch[n]], pi * c_cost[n]);
}

// ---------------------------------------------------------------------------
__global__ void final_kernel(const int* __restrict__ batch,
                             const float* __restrict__ B_total,
                             float* __restrict__ out) {
    int n = blockIdx.x * blockDim.x + threadIdx.x;
    if (n >= N_NODES) return;
    int b = batch[n];
    float ratio = fminf(B_total[b] / (g_texp[b] + 1e-12f), 1.f);
    out[n] = g_pi[n] * ratio;
}

// ---------------------------------------------------------------------------
extern "C" void kernel_launch(void* const* d_in, const int* in_sizes, int n_in,
                              void* d_out, int out_size) {
    const float* x       = (const float*)d_in[0];
    const int*   ei      = (const int*)d_in[1];     // int64 in reference -> int32 from harness
    const float* eattr   = (const float*)d_in[2];
    const int*   batch   = (const int*)d_in[3];     // int64 in reference -> int32 from harness
    const float* B_total = (const float*)d_in[4];
    const int*   term    = (const int*)d_in[5];
    const float* c_cost  = (const float*)d_in[6];
    const float* We1 = (const float*)d_in[7];
    const float* be1 = (const float*)d_in[8];
    const float* W1a = (const float*)d_in[9];
    const float* b1a = (const float*)d_in[10];
    const float* W1b = (const float*)d_in[11];
    const float* b1b = (const float*)d_in[12];
    const float* We2 = (const float*)d_in[13];
    const float* be2 = (const float*)d_in[14];
    const float* W2a = (const float*)d_in[15];
    const float* b2a = (const float*)d_in[16];
    const float* W2b = (const float*)d_in[17];
    const float* b2b = (const float*)d_in[18];
    const float* Wr1 = (const float*)d_in[19];
    const float* br1 = (const float*)d_in[20];
    const float* Wr2 = (const float*)d_in[21];
    const float* br2 = (const float*)d_in[22];
    float* out = (float*)d_out;

    const int NB_NODE = (N_NODES + 255) / 256;

    zero_agg_kernel<<<1600, 256>>>();
    edge1_kernel<<<(N_EDGES + 255) / 256, 256>>>(x, ei, eattr, We1, be1);
    mlp1_kernel<<<NB_NODE, 256>>>(x, W1a, b1a, W1b, b1b);
    zero_agg_kernel<<<1600, 256>>>();
    edge2_kernel<<<N_EDGES / 16, 256>>>(ei, eattr, We2, be2);
    mlp2_kernel<<<NB_NODE, 256>>>(W2a, b2a, W2b, b2b, Wr1, br1, Wr2, br2,
                                  batch, term, c_cost);
    final_kernel<<<NB_NODE, 256>>>(batch, B_total, out);
}